// round 1
// baseline (speedup 1.0000x reference)
#include <cuda_runtime.h>
#include <cuda_bf16.h>

// Problem constants (fixed shapes from setup_inputs)
#define NSRC0 400000
#define NDST0 40000
#define NDST1 4000
#define DF    256     // feature dim (in = hid = out = 256)

// ---------------------------------------------------------------------------
// Scratch (device globals; allocation-free per harness rules)
// ---------------------------------------------------------------------------
__device__ float g_agg0[NDST0 * DF];   // segment-sum of normalized x   [40000,256]
__device__ float g_h[NDST0 * DF];      // layer-1 output                [40000,256]
__device__ float g_agg1[NDST1 * DF];   // segment-sum of h              [4000,256]
__device__ float g_deg_out0[NSRC0];
__device__ float g_deg_in0[NDST0];
__device__ float g_deg_out1[NDST0];
__device__ float g_deg_in1[NDST1];

// ---------------------------------------------------------------------------
// Zero kernel (float4)
// ---------------------------------------------------------------------------
__global__ void zero_kernel(float4* __restrict__ p, int n4) {
    int i = blockIdx.x * blockDim.x + threadIdx.x;
    if (i < n4) p[i] = make_float4(0.f, 0.f, 0.f, 0.f);
}

// ---------------------------------------------------------------------------
// Degree kernel: float counts via RED atomics (exact for counts < 2^24)
// ---------------------------------------------------------------------------
__global__ void degree_kernel(const int* __restrict__ src0, const int* __restrict__ dst0,
                              const int* __restrict__ src1, const int* __restrict__ dst1,
                              float* __restrict__ deg_out0, float* __restrict__ deg_in0,
                              float* __restrict__ deg_out1, float* __restrict__ deg_in1,
                              int E0, int E1) {
    int i = blockIdx.x * blockDim.x + threadIdx.x;
    if (i < E0) {
        atomicAdd(&deg_out0[src0[i]], 1.f);
        atomicAdd(&deg_in0[dst0[i]], 1.f);
    }
    if (i < E1) {
        atomicAdd(&deg_out1[src1[i]], 1.f);
        atomicAdd(&deg_in1[dst1[i]], 1.f);
    }
}

// ---------------------------------------------------------------------------
// Vectorized global reduction: red.global.add.v4.f32 (sm_90+)
// ---------------------------------------------------------------------------
__device__ __forceinline__ void red_add_v4(float4* addr, float4 v) {
    asm volatile("red.global.add.v4.f32 [%0], {%1, %2, %3, %4};"
                 :: "l"(addr), "f"(v.x), "f"(v.y), "f"(v.z), "f"(v.w)
                 : "memory");
}

// ---------------------------------------------------------------------------
// Scatter: agg[dst[e]] += x[src[e]] * rsqrt(max(deg_out[src[e]],1))
// 64 threads per edge, each handles one float4 (256 feats).
// ---------------------------------------------------------------------------
__global__ void scatter_kernel(const float4* __restrict__ xin,
                               const int* __restrict__ src, const int* __restrict__ dst,
                               const float* __restrict__ deg_out,
                               float4* __restrict__ agg, int E) {
    int idx = blockIdx.x * blockDim.x + threadIdx.x;
    int e = idx >> 6;
    int g = idx & 63;
    if (e >= E) return;
    int s = src[e];
    int d = dst[e];
    float rs = rsqrtf(fmaxf(deg_out[s], 1.f));
    float4 v = xin[(long long)s * 64 + g];
    v.x *= rs; v.y *= rs; v.z *= rs; v.w *= rs;
    red_add_v4(agg + (long long)d * 64 + g, v);
}

// ---------------------------------------------------------------------------
// Fused SGEMM + epilogue:
//   C[M,256] = relu( (A[M,256] @ W[256,256]) * rsqrt(max(deg_in,1))[:,None] + bias )
// BM=128, BN=128, BK=8, 256 threads, 8x8 per-thread tile (split 4+4 in M and N
// for conflict-free float4 smem reads).
// ---------------------------------------------------------------------------
__global__ __launch_bounds__(256, 2)
void gemm_bias_relu(const float* __restrict__ A, const float* __restrict__ W,
                    const float* __restrict__ bias, const float* __restrict__ deg_in,
                    float* __restrict__ C, int M) {
    __shared__ float As[8][128];
    __shared__ float Bs[8][128];

    int tid = threadIdx.x;
    int tx = tid & 15;          // 0..15 (N direction)
    int ty = tid >> 4;          // 0..15 (M direction)
    int m0 = blockIdx.y * 128;
    int n0 = blockIdx.x * 128;

    float acc[8][8];
#pragma unroll
    for (int i = 0; i < 8; i++)
#pragma unroll
        for (int j = 0; j < 8; j++) acc[i][j] = 0.f;

    // Load mapping
    int arow = tid >> 1;          // 0..127
    int acol = (tid & 1) * 4;     // 0 or 4
    int brow = tid >> 5;          // 0..7
    int bcol = (tid & 31) * 4;    // 0..124
    bool arow_ok = (m0 + arow) < M;
    const float* Aptr = A + (long long)(m0 + arow) * 256 + acol;

    for (int k0 = 0; k0 < 256; k0 += 8) {
        float4 av = arow_ok ? *(const float4*)(Aptr + k0) : make_float4(0.f, 0.f, 0.f, 0.f);
        As[acol + 0][arow] = av.x;
        As[acol + 1][arow] = av.y;
        As[acol + 2][arow] = av.z;
        As[acol + 3][arow] = av.w;
        *(float4*)&Bs[brow][bcol] = *(const float4*)(W + (long long)(k0 + brow) * 256 + n0 + bcol);
        __syncthreads();
#pragma unroll
        for (int kk = 0; kk < 8; kk++) {
            float a[8], b[8];
            *(float4*)&a[0] = *(const float4*)&As[kk][ty * 4];
            *(float4*)&a[4] = *(const float4*)&As[kk][64 + ty * 4];
            *(float4*)&b[0] = *(const float4*)&Bs[kk][tx * 4];
            *(float4*)&b[4] = *(const float4*)&Bs[kk][64 + tx * 4];
#pragma unroll
            for (int i = 0; i < 8; i++)
#pragma unroll
                for (int j = 0; j < 8; j++)
                    acc[i][j] = fmaf(a[i], b[j], acc[i][j]);
        }
        __syncthreads();
    }

    // Epilogue: per-row rsqrt scale, per-col bias, relu
#pragma unroll
    for (int i = 0; i < 8; i++) {
        int rloc = (i < 4) ? (ty * 4 + i) : (64 + ty * 4 + (i - 4));
        int row = m0 + rloc;
        if (row >= M) continue;
        float rs = rsqrtf(fmaxf(deg_in[row], 1.f));
#pragma unroll
        for (int half = 0; half < 2; half++) {
            int cloc = half * 64 + tx * 4;
            int jb = half * 4;
            float4 o;
            o.x = fmaxf(fmaf(acc[i][jb + 0], rs, bias[n0 + cloc + 0]), 0.f);
            o.y = fmaxf(fmaf(acc[i][jb + 1], rs, bias[n0 + cloc + 1]), 0.f);
            o.z = fmaxf(fmaf(acc[i][jb + 2], rs, bias[n0 + cloc + 2]), 0.f);
            o.w = fmaxf(fmaf(acc[i][jb + 3], rs, bias[n0 + cloc + 3]), 0.f);
            *(float4*)(C + (long long)row * 256 + n0 + cloc) = o;
        }
    }
}

// ---------------------------------------------------------------------------
// Launch
// ---------------------------------------------------------------------------
extern "C" void kernel_launch(void* const* d_in, const int* in_sizes, int n_in,
                              void* d_out, int out_size) {
    const float* x   = (const float*)d_in[0];
    const int*  src0 = (const int*)d_in[1];
    const int*  dst0 = (const int*)d_in[2];
    const int*  src1 = (const int*)d_in[3];
    const int*  dst1 = (const int*)d_in[4];
    const float* W0  = (const float*)d_in[5];
    const float* b0  = (const float*)d_in[6];
    const float* W1  = (const float*)d_in[7];
    const float* b1  = (const float*)d_in[8];

    int E0 = in_sizes[1];
    int E1 = in_sizes[3];

    float *agg0, *h, *agg1, *dg_o0, *dg_i0, *dg_o1, *dg_i1;
    cudaGetSymbolAddress((void**)&agg0,  g_agg0);
    cudaGetSymbolAddress((void**)&h,     g_h);
    cudaGetSymbolAddress((void**)&agg1,  g_agg1);
    cudaGetSymbolAddress((void**)&dg_o0, g_deg_out0);
    cudaGetSymbolAddress((void**)&dg_i0, g_deg_in0);
    cudaGetSymbolAddress((void**)&dg_o1, g_deg_out1);
    cudaGetSymbolAddress((void**)&dg_i1, g_deg_in1);

    // 1. Zero accumulators + degree arrays
    {
        int n4;
        n4 = NDST0 * DF / 4; zero_kernel<<<(n4 + 255) / 256, 256>>>((float4*)agg0, n4);
        n4 = NDST1 * DF / 4; zero_kernel<<<(n4 + 255) / 256, 256>>>((float4*)agg1, n4);
        n4 = NSRC0 / 4;      zero_kernel<<<(n4 + 255) / 256, 256>>>((float4*)dg_o0, n4);
        n4 = NDST0 / 4;      zero_kernel<<<(n4 + 255) / 256, 256>>>((float4*)dg_i0, n4);
        n4 = NDST0 / 4;      zero_kernel<<<(n4 + 255) / 256, 256>>>((float4*)dg_o1, n4);
        n4 = NDST1 / 4;      zero_kernel<<<(n4 + 255) / 256, 256>>>((float4*)dg_i1, n4);
    }

    // 2. Degrees
    degree_kernel<<<(E0 + 255) / 256, 256>>>(src0, dst0, src1, dst1,
                                             dg_o0, dg_i0, dg_o1, dg_i1, E0, E1);

    // 3. Layer 0 scatter: agg0 = segment_sum((x * rsqrt(deg_out0))[src0], dst0)
    {
        long long nt = (long long)E0 * 64;
        scatter_kernel<<<(unsigned)((nt + 255) / 256), 256>>>(
            (const float4*)x, src0, dst0, dg_o0, (float4*)agg0, E0);
    }

    // 4. Layer 0 GEMM + scale + bias + relu -> h
    {
        dim3 grid(2, (NDST0 + 127) / 128);
        gemm_bias_relu<<<grid, 256>>>(agg0, W0, b0, dg_i0, h, NDST0);
    }

    // 5. Layer 1 scatter: agg1 = segment_sum((h * rsqrt(deg_out1))[src1], dst1)
    {
        long long nt = (long long)E1 * 64;
        scatter_kernel<<<(unsigned)((nt + 255) / 256), 256>>>(
            (const float4*)h, src1, dst1, dg_o1, (float4*)agg1, E1);
    }

    // 6. Layer 1 GEMM + scale + bias + relu -> out
    {
        dim3 grid(2, (NDST1 + 127) / 128);
        gemm_bias_relu<<<grid, 256>>>(agg1, W1, b1, dg_i1, (float*)d_out, NDST1);
    }
}

// round 3
// speedup vs baseline: 1.3041x; 1.3041x over previous
#include <cuda_runtime.h>
#include <cuda_bf16.h>
#include <cstdint>

// Problem constants (fixed shapes from setup_inputs)
#define NSRC0 400000
#define NDST0 40000
#define NDST1 4000
#define DF    256

// ---------------------------------------------------------------------------
// Scratch (device globals; allocation-free per harness rules)
// ---------------------------------------------------------------------------
__device__ float g_agg0[NDST0 * DF];
__device__ float g_h[NDST0 * DF];
__device__ float g_agg1[NDST1 * DF];
__device__ float g_deg_out0[NSRC0];
__device__ float g_deg_in0[NDST0];
__device__ float g_deg_out1[NDST0];
__device__ float g_deg_in1[NDST1];
// W transposed [n][k], split hi/lo bf16, per layer
__device__ __nv_bfloat16 g_Whi[2][256 * 256];
__device__ __nv_bfloat16 g_Wlo[2][256 * 256];

// ---------------------------------------------------------------------------
// Helpers
// ---------------------------------------------------------------------------
__device__ __forceinline__ uint32_t smem_u32(const void* p) {
    uint32_t a;
    asm("{ .reg .u64 t; cvta.to.shared.u64 t, %1; cvt.u32.u64 %0, t; }" : "=r"(a) : "l"(p));
    return a;
}

__device__ __forceinline__ void ldsm4(uint32_t* r, uint32_t addr) {
    asm volatile("ldmatrix.sync.aligned.m8n8.x4.shared.b16 {%0,%1,%2,%3}, [%4];"
                 : "=r"(r[0]), "=r"(r[1]), "=r"(r[2]), "=r"(r[3]) : "r"(addr));
}

__device__ __forceinline__ void mma_bf16(float* c, const uint32_t* a, uint32_t b0, uint32_t b1) {
    asm volatile(
        "mma.sync.aligned.m16n8k16.row.col.f32.bf16.bf16.f32 "
        "{%0,%1,%2,%3}, {%4,%5,%6,%7}, {%8,%9}, {%0,%1,%2,%3};"
        : "+f"(c[0]), "+f"(c[1]), "+f"(c[2]), "+f"(c[3])
        : "r"(a[0]), "r"(a[1]), "r"(a[2]), "r"(a[3]), "r"(b0), "r"(b1));
}

// ---------------------------------------------------------------------------
// Zero kernel (float4)
// ---------------------------------------------------------------------------
__global__ void zero_kernel(float4* __restrict__ p, int n4) {
    int i = blockIdx.x * blockDim.x + threadIdx.x;
    if (i < n4) p[i] = make_float4(0.f, 0.f, 0.f, 0.f);
}

// ---------------------------------------------------------------------------
// Degree kernel
// ---------------------------------------------------------------------------
__global__ void degree_kernel(const int* __restrict__ src0, const int* __restrict__ dst0,
                              const int* __restrict__ src1, const int* __restrict__ dst1,
                              float* __restrict__ deg_out0, float* __restrict__ deg_in0,
                              float* __restrict__ deg_out1, float* __restrict__ deg_in1,
                              int E0, int E1) {
    int i = blockIdx.x * blockDim.x + threadIdx.x;
    if (i < E0) {
        atomicAdd(&deg_out0[src0[i]], 1.f);
        atomicAdd(&deg_in0[dst0[i]], 1.f);
    }
    if (i < E1) {
        atomicAdd(&deg_out1[src1[i]], 1.f);
        atomicAdd(&deg_in1[dst1[i]], 1.f);
    }
}

// ---------------------------------------------------------------------------
// W prep: split fp32 W[k][n] -> transposed bf16 hi/lo Wt[n][k]
// grid = (256 n, 2 layers), block = 256 k
// ---------------------------------------------------------------------------
__global__ void prep_w_kernel(const float* __restrict__ W0, const float* __restrict__ W1) {
    int layer = blockIdx.y;
    const float* W = layer ? W1 : W0;
    int n = blockIdx.x;
    int k = threadIdx.x;
    float w = W[k * 256 + n];
    __nv_bfloat16 hi = __float2bfloat16(w);
    __nv_bfloat16 lo = __float2bfloat16(w - __bfloat162float(hi));
    g_Whi[layer][n * 256 + k] = hi;
    g_Wlo[layer][n * 256 + k] = lo;
}

// ---------------------------------------------------------------------------
// Scatter (vectorized global reduction)
// ---------------------------------------------------------------------------
__device__ __forceinline__ void red_add_v4(float4* addr, float4 v) {
    asm volatile("red.global.add.v4.f32 [%0], {%1, %2, %3, %4};"
                 :: "l"(addr), "f"(v.x), "f"(v.y), "f"(v.z), "f"(v.w)
                 : "memory");
}

__global__ void scatter_kernel(const float4* __restrict__ xin,
                               const int* __restrict__ src, const int* __restrict__ dst,
                               const float* __restrict__ deg_out,
                               float4* __restrict__ agg, int E) {
    int idx = blockIdx.x * blockDim.x + threadIdx.x;
    int e = idx >> 6;
    int g = idx & 63;
    if (e >= E) return;
    int s = src[e];
    int d = dst[e];
    float rs = rsqrtf(fmaxf(deg_out[s], 1.f));
    float4 v = xin[s * 64 + g];
    v.x *= rs; v.y *= rs; v.z *= rs; v.w *= rs;
    red_add_v4(agg + d * 64 + g, v);
}

// ---------------------------------------------------------------------------
// Tensor-core GEMM (mma.sync bf16, 3-pass split precision) + fused epilogue:
//   C[M,256] = relu((A @ W) * rsqrt(max(deg_in,1))[:,None] + bias)
// CTA: BM=128 x BN=128, BK=32. 8 warps (4m x 2n), warp tile 32x64.
// B comes pre-transposed/split: Wt[n][k] bf16.
// ---------------------------------------------------------------------------
#define PADK 40   // smem row stride in bf16 (80 B) -> conflict-free ldmatrix

__global__ __launch_bounds__(256)
void gemm_mma(const float* __restrict__ A,
              const __nv_bfloat16* __restrict__ Bhi, const __nv_bfloat16* __restrict__ Blo,
              const float* __restrict__ bias, const float* __restrict__ deg_in,
              float* __restrict__ C, int M) {
    __shared__ __nv_bfloat16 sAh[128 * PADK];
    __shared__ __nv_bfloat16 sAl[128 * PADK];
    __shared__ __nv_bfloat16 sBh[128 * PADK];
    __shared__ __nv_bfloat16 sBl[128 * PADK];

    int tid = threadIdx.x;
    int wid = tid >> 5, lid = tid & 31;
    int wm = wid & 3, wn = wid >> 2;         // warp coords: 4 (m) x 2 (n)
    int m0 = blockIdx.y * 128;
    int n0 = blockIdx.x * 128;

    uint32_t sAh_b = smem_u32(sAh), sAl_b = smem_u32(sAl);
    uint32_t sBh_b = smem_u32(sBh), sBl_b = smem_u32(sBl);

    float acc[2][8][4];
#pragma unroll
    for (int i = 0; i < 2; i++)
#pragma unroll
        for (int j = 0; j < 8; j++)
#pragma unroll
            for (int q = 0; q < 4; q++) acc[i][j][q] = 0.f;

    int lr = lid & 7, lmat = lid >> 3;       // ldmatrix lane roles

    for (int kt = 0; kt < 8; kt++) {
        int k0 = kt * 32;
        // ---- load A tile (fp32 -> split bf16 hi/lo) ----
#pragma unroll
        for (int i = 0; i < 4; i++) {
            int v = tid + i * 256;            // 0..1023 float4s (128 rows x 8)
            int row = v >> 3, kq = (v & 7) * 4;
            float4 a = make_float4(0.f, 0.f, 0.f, 0.f);
            if (m0 + row < M) a = *(const float4*)(A + (m0 + row) * 256 + k0 + kq);
            __nv_bfloat162 h01 = __floats2bfloat162_rn(a.x, a.y);
            __nv_bfloat162 h23 = __floats2bfloat162_rn(a.z, a.w);
            __nv_bfloat162 l01 = __floats2bfloat162_rn(
                a.x - __bfloat162float(h01.x), a.y - __bfloat162float(h01.y));
            __nv_bfloat162 l23 = __floats2bfloat162_rn(
                a.z - __bfloat162float(h23.x), a.w - __bfloat162float(h23.y));
            int off = row * PADK + kq;
            *(__nv_bfloat162*)&sAh[off] = h01;
            *(__nv_bfloat162*)&sAh[off + 2] = h23;
            *(__nv_bfloat162*)&sAl[off] = l01;
            *(__nv_bfloat162*)&sAl[off + 2] = l23;
        }
        // ---- load B tiles (already bf16, [n][k] row-major) ----
#pragma unroll
        for (int i = 0; i < 2; i++) {
            int v = tid + i * 256;            // 0..511 (128 rows x 4 chunks of 8 bf16)
            int row = v >> 2, kc = (v & 3) * 8;
            const __nv_bfloat16* gh = Bhi + (n0 + row) * 256 + k0 + kc;
            const __nv_bfloat16* gl = Blo + (n0 + row) * 256 + k0 + kc;
            *(uint4*)&sBh[row * PADK + kc] = *(const uint4*)gh;
            *(uint4*)&sBl[row * PADK + kc] = *(const uint4*)gl;
        }
        __syncthreads();

#pragma unroll
        for (int kk = 0; kk < 32; kk += 16) {
            uint32_t ah[2][4], al[2][4], bh[4][4], bl[4][4];
            // A fragments: mats {m0k0, m8k0, m0k8, m8k8}
#pragma unroll
            for (int mi = 0; mi < 2; mi++) {
                int arow = wm * 32 + mi * 16 + (lmat & 1) * 8 + lr;
                int akol = kk + (lmat >> 1) * 8;
                uint32_t off = (uint32_t)(arow * PADK + akol) * 2;
                ldsm4(ah[mi], sAh_b + off);
                ldsm4(al[mi], sAl_b + off);
            }
            // B fragments: mats {n0kk, n0kk8, n8kk, n8kk8}
#pragma unroll
            for (int ni = 0; ni < 4; ni++) {
                int brow = wn * 64 + ni * 16 + (lmat >> 1) * 8 + lr;
                int bkol = kk + (lmat & 1) * 8;
                uint32_t off = (uint32_t)(brow * PADK + bkol) * 2;
                ldsm4(bh[ni], sBh_b + off);
                ldsm4(bl[ni], sBl_b + off);
            }
            // 3 passes: hi*hi, lo*hi, hi*lo
#pragma unroll
            for (int mi = 0; mi < 2; mi++)
#pragma unroll
                for (int nj = 0; nj < 8; nj++) {
                    uint32_t b0h = bh[nj >> 1][(nj & 1) * 2];
                    uint32_t b1h = bh[nj >> 1][(nj & 1) * 2 + 1];
                    uint32_t b0l = bl[nj >> 1][(nj & 1) * 2];
                    uint32_t b1l = bl[nj >> 1][(nj & 1) * 2 + 1];
                    mma_bf16(acc[mi][nj], ah[mi], b0h, b1h);
                    mma_bf16(acc[mi][nj], al[mi], b0h, b1h);
                    mma_bf16(acc[mi][nj], ah[mi], b0l, b1l);
                }
        }
        __syncthreads();
    }

    // ---- epilogue: scale by rsqrt(deg_in), + bias, relu ----
#pragma unroll
    for (int mi = 0; mi < 2; mi++) {
        int ra = m0 + wm * 32 + mi * 16 + (lid >> 2);
        int rb = ra + 8;
        float rsa = (ra < M) ? rsqrtf(fmaxf(deg_in[ra], 1.f)) : 0.f;
        float rsb = (rb < M) ? rsqrtf(fmaxf(deg_in[rb], 1.f)) : 0.f;
#pragma unroll
        for (int nj = 0; nj < 8; nj++) {
            int col = n0 + wn * 64 + nj * 8 + (lid & 3) * 2;
            float b0 = bias[col], b1 = bias[col + 1];
            if (ra < M) {
                float2 o;
                o.x = fmaxf(fmaf(acc[mi][nj][0], rsa, b0), 0.f);
                o.y = fmaxf(fmaf(acc[mi][nj][1], rsa, b1), 0.f);
                *(float2*)(C + ra * 256 + col) = o;
            }
            if (rb < M) {
                float2 o;
                o.x = fmaxf(fmaf(acc[mi][nj][2], rsb, b0), 0.f);
                o.y = fmaxf(fmaf(acc[mi][nj][3], rsb, b1), 0.f);
                *(float2*)(C + rb * 256 + col) = o;
            }
        }
    }
}

// ---------------------------------------------------------------------------
// Launch
// ---------------------------------------------------------------------------
extern "C" void kernel_launch(void* const* d_in, const int* in_sizes, int n_in,
                              void* d_out, int out_size) {
    const float* x   = (const float*)d_in[0];
    const int*  src0 = (const int*)d_in[1];
    const int*  dst0 = (const int*)d_in[2];
    const int*  src1 = (const int*)d_in[3];
    const int*  dst1 = (const int*)d_in[4];
    const float* W0  = (const float*)d_in[5];
    const float* b0  = (const float*)d_in[6];
    const float* W1  = (const float*)d_in[7];
    const float* b1  = (const float*)d_in[8];

    int E0 = in_sizes[1];
    int E1 = in_sizes[3];

    float *agg0, *h, *agg1, *dg_o0, *dg_i0, *dg_o1, *dg_i1;
    __nv_bfloat16 *whi, *wlo;
    cudaGetSymbolAddress((void**)&agg0,  g_agg0);
    cudaGetSymbolAddress((void**)&h,     g_h);
    cudaGetSymbolAddress((void**)&agg1,  g_agg1);
    cudaGetSymbolAddress((void**)&dg_o0, g_deg_out0);
    cudaGetSymbolAddress((void**)&dg_i0, g_deg_in0);
    cudaGetSymbolAddress((void**)&dg_o1, g_deg_out1);
    cudaGetSymbolAddress((void**)&dg_i1, g_deg_in1);
    cudaGetSymbolAddress((void**)&whi,   g_Whi);
    cudaGetSymbolAddress((void**)&wlo,   g_Wlo);

    // 1. Zero accumulators + degree arrays
    {
        int n4;
        n4 = NDST0 * DF / 4; zero_kernel<<<(n4 + 255) / 256, 256>>>((float4*)agg0, n4);
        n4 = NDST1 * DF / 4; zero_kernel<<<(n4 + 255) / 256, 256>>>((float4*)agg1, n4);
        n4 = NSRC0 / 4;      zero_kernel<<<(n4 + 255) / 256, 256>>>((float4*)dg_o0, n4);
        n4 = NDST0 / 4;      zero_kernel<<<(n4 + 255) / 256, 256>>>((float4*)dg_i0, n4);
        n4 = NDST0 / 4;      zero_kernel<<<(n4 + 255) / 256, 256>>>((float4*)dg_o1, n4);
        n4 = NDST1 / 4;      zero_kernel<<<(n4 + 255) / 256, 256>>>((float4*)dg_i1, n4);
    }

    // 2. Degrees + weight prep
    degree_kernel<<<(E0 + 255) / 256, 256>>>(src0, dst0, src1, dst1,
                                             dg_o0, dg_i0, dg_o1, dg_i1, E0, E1);
    prep_w_kernel<<<dim3(256, 2), 256>>>(W0, W1);

    // 3. Layer 0 scatter
    {
        long long nt = (long long)E0 * 64;
        scatter_kernel<<<(unsigned)((nt + 255) / 256), 256>>>(
            (const float4*)x, src0, dst0, dg_o0, (float4*)agg0, E0);
    }

    // 4. Layer 0 GEMM (tensor cores, split bf16) -> h
    {
        dim3 grid(2, (NDST0 + 127) / 128);
        gemm_mma<<<grid, 256>>>(agg0, whi, wlo, b0, dg_i0, h, NDST0);
    }

    // 5. Layer 1 scatter
    {
        long long nt = (long long)E1 * 64;
        scatter_kernel<<<(unsigned)((nt + 255) / 256), 256>>>(
            (const float4*)h, src1, dst1, dg_o1, (float4*)agg1, E1);
    }

    // 6. Layer 1 GEMM -> out
    {
        dim3 grid(2, (NDST1 + 127) / 128);
        gemm_mma<<<grid, 256>>>(agg1, whi + 65536, wlo + 65536, b1, dg_i1,
                                (float*)d_out, NDST1);
    }
}

// round 4
// speedup vs baseline: 1.4261x; 1.0935x over previous
#include <cuda_runtime.h>
#include <cuda_bf16.h>
#include <cstdint>

// Problem constants (fixed shapes from setup_inputs)
#define NSRC0 400000
#define NDST0 40000
#define NDST1 4000
#define DF    256

// ---------------------------------------------------------------------------
// Scratch (device globals; allocation-free per harness rules)
// ---------------------------------------------------------------------------
__device__ float g_agg0[NDST0 * DF];
__device__ float g_h[NDST0 * DF];
__device__ float g_agg1[NDST1 * DF];
// W transposed [n][k], split hi/lo bf16, per layer
__device__ __nv_bfloat16 g_Whi[2][256 * 256];
__device__ __nv_bfloat16 g_Wlo[2][256 * 256];

// Int scratch, one contiguous block so a single zero kernel covers the
// parts that need zeroing (first IZERO ints).
//   [0,400000)        cnt_out0   (out-degree of x nodes)
//   [400000,440000)   cnt_in0    (in-degree of layer-0 dsts)
//   [440000,480000)   cur0       (bucket cursors, layer 0)
//   [480000,520000)   cnt_out1   (out-degree of h nodes)
//   [520000,524000)   cnt_in1
//   [524000,528000)   cur1
//   [528000,568000)   off0       (scan output, no zeroing)
//   [568000,572000)   off1
//   [572000,972000)   bsrc0      (bucketed src ids, layer 0)
//   [972000,1012000)  bsrc1
#define I_CNT_OUT0 0
#define I_CNT_IN0  400000
#define I_CUR0     440000
#define I_CNT_OUT1 480000
#define I_CNT_IN1  520000
#define I_CUR1     524000
#define I_OFF0     528000
#define I_OFF1     568000
#define I_BSRC0    572000
#define I_BSRC1    972000
#define IZERO      528000
__device__ int g_ints[1012000];

// ---------------------------------------------------------------------------
// Helpers
// ---------------------------------------------------------------------------
__device__ __forceinline__ uint32_t smem_u32(const void* p) {
    uint32_t a;
    asm("{ .reg .u64 t; cvta.to.shared.u64 t, %1; cvt.u32.u64 %0, t; }" : "=r"(a) : "l"(p));
    return a;
}

__device__ __forceinline__ void ldsm4(uint32_t* r, uint32_t addr) {
    asm volatile("ldmatrix.sync.aligned.m8n8.x4.shared.b16 {%0,%1,%2,%3}, [%4];"
                 : "=r"(r[0]), "=r"(r[1]), "=r"(r[2]), "=r"(r[3]) : "r"(addr));
}

__device__ __forceinline__ void mma_bf16(float* c, const uint32_t* a, uint32_t b0, uint32_t b1) {
    asm volatile(
        "mma.sync.aligned.m16n8k16.row.col.f32.bf16.bf16.f32 "
        "{%0,%1,%2,%3}, {%4,%5,%6,%7}, {%8,%9}, {%0,%1,%2,%3};"
        : "+f"(c[0]), "+f"(c[1]), "+f"(c[2]), "+f"(c[3])
        : "r"(a[0]), "r"(a[1]), "r"(a[2]), "r"(a[3]), "r"(b0), "r"(b1));
}

// ---------------------------------------------------------------------------
// Zero kernel (int4)
// ---------------------------------------------------------------------------
__global__ void zero_ints(int4* __restrict__ p, int n4) {
    int i = blockIdx.x * blockDim.x + threadIdx.x;
    if (i < n4) p[i] = make_int4(0, 0, 0, 0);
}

// ---------------------------------------------------------------------------
// Degree counts (int atomics)
// ---------------------------------------------------------------------------
__global__ void degree_kernel(const int* __restrict__ src0, const int* __restrict__ dst0,
                              const int* __restrict__ src1, const int* __restrict__ dst1,
                              int E0, int E1) {
    int i = blockIdx.x * blockDim.x + threadIdx.x;
    if (i < E0) {
        atomicAdd(&g_ints[I_CNT_OUT0 + src0[i]], 1);
        atomicAdd(&g_ints[I_CNT_IN0 + dst0[i]], 1);
    }
    if (i < E1) {
        atomicAdd(&g_ints[I_CNT_OUT1 + src1[i]], 1);
        atomicAdd(&g_ints[I_CNT_IN1 + dst1[i]], 1);
    }
}

// ---------------------------------------------------------------------------
// One-block exclusive prefix scan (n up to a few 100k; 1024 threads)
// ---------------------------------------------------------------------------
__global__ void scan_kernel(const int* __restrict__ cnt, int* __restrict__ off, int n) {
    __shared__ int warp_sums[32];
    __shared__ int s_carry;
    int tid = threadIdx.x;
    if (tid == 0) s_carry = 0;
    __syncthreads();
    for (int base = 0; base < n; base += 1024) {
        int v = (base + tid < n) ? cnt[base + tid] : 0;
        int x = v;
#pragma unroll
        for (int d = 1; d < 32; d <<= 1) {
            int y = __shfl_up_sync(~0u, x, d);
            if ((tid & 31) >= d) x += y;
        }
        if ((tid & 31) == 31) warp_sums[tid >> 5] = x;
        __syncthreads();
        if (tid < 32) {
            int w = warp_sums[tid];
#pragma unroll
            for (int d = 1; d < 32; d <<= 1) {
                int y = __shfl_up_sync(~0u, w, d);
                if (tid >= d) w += y;
            }
            warp_sums[tid] = w;
        }
        __syncthreads();
        int warp_excl = (tid >= 32) ? warp_sums[(tid >> 5) - 1] : 0;
        if (base + tid < n) off[base + tid] = x - v + warp_excl + s_carry;
        __syncthreads();
        if (tid == 0) s_carry += warp_sums[31];
        __syncthreads();
    }
}

// ---------------------------------------------------------------------------
// Bucket edges by dst: bsrc[off[d] + cursor[d]++] = src[e]
// ---------------------------------------------------------------------------
__global__ void bucket_kernel(const int* __restrict__ src0, const int* __restrict__ dst0,
                              const int* __restrict__ src1, const int* __restrict__ dst1,
                              int E0, int E1) {
    int i = blockIdx.x * blockDim.x + threadIdx.x;
    if (i < E0) {
        int d = dst0[i];
        int pos = g_ints[I_OFF0 + d] + atomicAdd(&g_ints[I_CUR0 + d], 1);
        g_ints[I_BSRC0 + pos] = src0[i];
    }
    if (i < E1) {
        int d = dst1[i];
        int pos = g_ints[I_OFF1 + d] + atomicAdd(&g_ints[I_CUR1 + d], 1);
        g_ints[I_BSRC1 + pos] = src1[i];
    }
}

// ---------------------------------------------------------------------------
// CSR gather: one warp per dst row.
//   agg[d] = sum_{e in bucket(d)} x[src_e] * rsqrt(max(deg_out[src_e],1))
// Lane owns 8 feats (2 float4, cols lane*4 and 128+lane*4). No atomics;
// each agg row written exactly once (zeros if degree 0).
// ---------------------------------------------------------------------------
__global__ void gather_kernel(const float4* __restrict__ xin,
                              const int* __restrict__ bsrc,
                              const int* __restrict__ off, const int* __restrict__ cnt,
                              const int* __restrict__ cnt_out,
                              float4* __restrict__ agg, int ndst) {
    int w = (blockIdx.x * blockDim.x + threadIdx.x) >> 5;
    if (w >= ndst) return;
    int lane = threadIdx.x & 31;
    int s0 = off[w];
    int c = cnt[w];
    float4 a0 = make_float4(0.f, 0.f, 0.f, 0.f);
    float4 a1 = make_float4(0.f, 0.f, 0.f, 0.f);
    for (int i = s0; i < s0 + c; i++) {
        int s = bsrc[i];                                 // broadcast load
        float rs = rsqrtf(fmaxf((float)cnt_out[s], 1.f)); // broadcast load
        const float4* row = xin + (long long)s * 64;
        float4 v0 = row[lane];
        float4 v1 = row[32 + lane];
        a0.x = fmaf(v0.x, rs, a0.x); a0.y = fmaf(v0.y, rs, a0.y);
        a0.z = fmaf(v0.z, rs, a0.z); a0.w = fmaf(v0.w, rs, a0.w);
        a1.x = fmaf(v1.x, rs, a1.x); a1.y = fmaf(v1.y, rs, a1.y);
        a1.z = fmaf(v1.z, rs, a1.z); a1.w = fmaf(v1.w, rs, a1.w);
    }
    agg[(long long)w * 64 + lane] = a0;
    agg[(long long)w * 64 + 32 + lane] = a1;
}

// ---------------------------------------------------------------------------
// W prep: split fp32 W[k][n] -> transposed bf16 hi/lo Wt[n][k]
// ---------------------------------------------------------------------------
__global__ void prep_w_kernel(const float* __restrict__ W0, const float* __restrict__ W1) {
    int layer = blockIdx.y;
    const float* W = layer ? W1 : W0;
    int n = blockIdx.x;
    int k = threadIdx.x;
    float w = W[k * 256 + n];
    __nv_bfloat16 hi = __float2bfloat16(w);
    __nv_bfloat16 lo = __float2bfloat16(w - __bfloat162float(hi));
    g_Whi[layer][n * 256 + k] = hi;
    g_Wlo[layer][n * 256 + k] = lo;
}

// ---------------------------------------------------------------------------
// Tensor-core GEMM (mma.sync bf16, 3-pass split precision) + fused epilogue:
//   C[M,256] = relu((A @ W) * rsqrt(max(deg_in,1))[:,None] + bias)
// CTA: BM=128 x BN=128, BK=32. 8 warps (4m x 2n), warp tile 32x64.
// ---------------------------------------------------------------------------
#define PADK 40   // smem row stride in bf16 (80 B) -> conflict-free ldmatrix

__global__ __launch_bounds__(256)
void gemm_mma(const float* __restrict__ A,
              const __nv_bfloat16* __restrict__ Bhi, const __nv_bfloat16* __restrict__ Blo,
              const float* __restrict__ bias, const int* __restrict__ deg_in,
              float* __restrict__ C, int M) {
    __shared__ __nv_bfloat16 sAh[128 * PADK];
    __shared__ __nv_bfloat16 sAl[128 * PADK];
    __shared__ __nv_bfloat16 sBh[128 * PADK];
    __shared__ __nv_bfloat16 sBl[128 * PADK];

    int tid = threadIdx.x;
    int wid = tid >> 5, lid = tid & 31;
    int wm = wid & 3, wn = wid >> 2;
    int m0 = blockIdx.y * 128;
    int n0 = blockIdx.x * 128;

    uint32_t sAh_b = smem_u32(sAh), sAl_b = smem_u32(sAl);
    uint32_t sBh_b = smem_u32(sBh), sBl_b = smem_u32(sBl);

    float acc[2][8][4];
#pragma unroll
    for (int i = 0; i < 2; i++)
#pragma unroll
        for (int j = 0; j < 8; j++)
#pragma unroll
            for (int q = 0; q < 4; q++) acc[i][j][q] = 0.f;

    int lr = lid & 7, lmat = lid >> 3;

    for (int kt = 0; kt < 8; kt++) {
        int k0 = kt * 32;
#pragma unroll
        for (int i = 0; i < 4; i++) {
            int v = tid + i * 256;
            int row = v >> 3, kq = (v & 7) * 4;
            float4 a = make_float4(0.f, 0.f, 0.f, 0.f);
            if (m0 + row < M) a = *(const float4*)(A + (m0 + row) * 256 + k0 + kq);
            __nv_bfloat162 h01 = __floats2bfloat162_rn(a.x, a.y);
            __nv_bfloat162 h23 = __floats2bfloat162_rn(a.z, a.w);
            __nv_bfloat162 l01 = __floats2bfloat162_rn(
                a.x - __bfloat162float(h01.x), a.y - __bfloat162float(h01.y));
            __nv_bfloat162 l23 = __floats2bfloat162_rn(
                a.z - __bfloat162float(h23.x), a.w - __bfloat162float(h23.y));
            int off = row * PADK + kq;
            *(__nv_bfloat162*)&sAh[off] = h01;
            *(__nv_bfloat162*)&sAh[off + 2] = h23;
            *(__nv_bfloat162*)&sAl[off] = l01;
            *(__nv_bfloat162*)&sAl[off + 2] = l23;
        }
#pragma unroll
        for (int i = 0; i < 2; i++) {
            int v = tid + i * 256;
            int row = v >> 2, kc = (v & 3) * 8;
            const __nv_bfloat16* gh = Bhi + (n0 + row) * 256 + k0 + kc;
            const __nv_bfloat16* gl = Blo + (n0 + row) * 256 + k0 + kc;
            *(uint4*)&sBh[row * PADK + kc] = *(const uint4*)gh;
            *(uint4*)&sBl[row * PADK + kc] = *(const uint4*)gl;
        }
        __syncthreads();

#pragma unroll
        for (int kk = 0; kk < 32; kk += 16) {
            uint32_t ah[2][4], al[2][4], bh[4][4], bl[4][4];
#pragma unroll
            for (int mi = 0; mi < 2; mi++) {
                int arow = wm * 32 + mi * 16 + (lmat & 1) * 8 + lr;
                int akol = kk + (lmat >> 1) * 8;
                uint32_t off = (uint32_t)(arow * PADK + akol) * 2;
                ldsm4(ah[mi], sAh_b + off);
                ldsm4(al[mi], sAl_b + off);
            }
#pragma unroll
            for (int ni = 0; ni < 4; ni++) {
                int brow = wn * 64 + ni * 16 + (lmat >> 1) * 8 + lr;
                int bkol = kk + (lmat & 1) * 8;
                uint32_t off = (uint32_t)(brow * PADK + bkol) * 2;
                ldsm4(bh[ni], sBh_b + off);
                ldsm4(bl[ni], sBl_b + off);
            }
#pragma unroll
            for (int mi = 0; mi < 2; mi++)
#pragma unroll
                for (int nj = 0; nj < 8; nj++) {
                    uint32_t b0h = bh[nj >> 1][(nj & 1) * 2];
                    uint32_t b1h = bh[nj >> 1][(nj & 1) * 2 + 1];
                    uint32_t b0l = bl[nj >> 1][(nj & 1) * 2];
                    uint32_t b1l = bl[nj >> 1][(nj & 1) * 2 + 1];
                    mma_bf16(acc[mi][nj], ah[mi], b0h, b1h);
                    mma_bf16(acc[mi][nj], al[mi], b0h, b1h);
                    mma_bf16(acc[mi][nj], ah[mi], b0l, b1l);
                }
        }
        __syncthreads();
    }

#pragma unroll
    for (int mi = 0; mi < 2; mi++) {
        int ra = m0 + wm * 32 + mi * 16 + (lid >> 2);
        int rb = ra + 8;
        float rsa = (ra < M) ? rsqrtf(fmaxf((float)deg_in[ra], 1.f)) : 0.f;
        float rsb = (rb < M) ? rsqrtf(fmaxf((float)deg_in[rb], 1.f)) : 0.f;
#pragma unroll
        for (int nj = 0; nj < 8; nj++) {
            int col = n0 + wn * 64 + nj * 8 + (lid & 3) * 2;
            float b0 = bias[col], b1 = bias[col + 1];
            if (ra < M) {
                float2 o;
                o.x = fmaxf(fmaf(acc[mi][nj][0], rsa, b0), 0.f);
                o.y = fmaxf(fmaf(acc[mi][nj][1], rsa, b1), 0.f);
                *(float2*)(C + ra * 256 + col) = o;
            }
            if (rb < M) {
                float2 o;
                o.x = fmaxf(fmaf(acc[mi][nj][2], rsb, b0), 0.f);
                o.y = fmaxf(fmaf(acc[mi][nj][3], rsb, b1), 0.f);
                *(float2*)(C + rb * 256 + col) = o;
            }
        }
    }
}

// ---------------------------------------------------------------------------
// Launch
// ---------------------------------------------------------------------------
extern "C" void kernel_launch(void* const* d_in, const int* in_sizes, int n_in,
                              void* d_out, int out_size) {
    const float* x   = (const float*)d_in[0];
    const int*  src0 = (const int*)d_in[1];
    const int*  dst0 = (const int*)d_in[2];
    const int*  src1 = (const int*)d_in[3];
    const int*  dst1 = (const int*)d_in[4];
    const float* W0  = (const float*)d_in[5];
    const float* b0  = (const float*)d_in[6];
    const float* W1  = (const float*)d_in[7];
    const float* b1  = (const float*)d_in[8];

    int E0 = in_sizes[1];
    int E1 = in_sizes[3];

    float *agg0, *h, *agg1;
    __nv_bfloat16 *whi, *wlo;
    int* ints;
    cudaGetSymbolAddress((void**)&agg0, g_agg0);
    cudaGetSymbolAddress((void**)&h,    g_h);
    cudaGetSymbolAddress((void**)&agg1, g_agg1);
    cudaGetSymbolAddress((void**)&whi,  g_Whi);
    cudaGetSymbolAddress((void**)&wlo,  g_Wlo);
    cudaGetSymbolAddress((void**)&ints, g_ints);

    // 1. Zero counters/cursors
    zero_ints<<<(IZERO / 4 + 255) / 256, 256>>>((int4*)ints, IZERO / 4);

    // 2. Weight prep (independent) + degree counts
    prep_w_kernel<<<dim3(256, 2), 256>>>(W0, W1);
    degree_kernel<<<(E0 + 255) / 256, 256>>>(src0, dst0, src1, dst1, E0, E1);

    // 3. Offsets via one-block scans
    scan_kernel<<<1, 1024>>>(ints + I_CNT_IN0, ints + I_OFF0, NDST0);
    scan_kernel<<<1, 1024>>>(ints + I_CNT_IN1, ints + I_OFF1, NDST1);

    // 4. Bucket edges by dst
    bucket_kernel<<<(E0 + 255) / 256, 256>>>(src0, dst0, src1, dst1, E0, E1);

    // 5. Layer 0 gather (CSR, no atomics)
    gather_kernel<<<(NDST0 * 32 + 255) / 256, 256>>>(
        (const float4*)x, ints + I_BSRC0, ints + I_OFF0, ints + I_CNT_IN0,
        ints + I_CNT_OUT0, (float4*)agg0, NDST0);

    // 6. Layer 0 GEMM -> h
    {
        dim3 grid(2, (NDST0 + 127) / 128);
        gemm_mma<<<grid, 256>>>(agg0, whi, wlo, b0, ints + I_CNT_IN0, h, NDST0);
    }

    // 7. Layer 1 gather
    gather_kernel<<<(NDST1 * 32 + 255) / 256, 256>>>(
        (const float4*)h, ints + I_BSRC1, ints + I_OFF1, ints + I_CNT_IN1,
        ints + I_CNT_OUT1, (float4*)agg1, NDST1);

    // 8. Layer 1 GEMM -> out
    {
        dim3 grid(2, (NDST1 + 127) / 128);
        gemm_mma<<<grid, 256>>>(agg1, whi + 65536, wlo + 65536, b1,
                                ints + I_CNT_IN1, (float*)d_out, NDST1);
    }
}